// round 2
// baseline (speedup 1.0000x reference)
#include <cuda_runtime.h>

#define BATCH 2
#define NPTS  262144
#define CH    64

// Tile geometry: logical rows r in [0,128) map to m = m0 - 3 + r.
// Valid final outputs: r in [3, 123)  => T = 120 outputs per tile.
// Buffers padded by 1 row on each side (logical -1 and 128) so the inner loop
// never clamps; garbage in pad rows is confined to invalid edge outputs.
constexpr int T       = 120;
constexpr int ROWS    = 128;
constexpr int PADROWS = 130;
constexpr int NTILES  = (NPTS + T - 1) / T;   // 2185
constexpr int SMEM_FLOATS = 3 * PADROWS * CH + 192 * CH + CH;

// ---- device scratch (no allocations allowed) ----
__device__ float g_h1[(size_t)BATCH * NPTS * CH];   // block-1 output, conv order (128 MiB)
__device__ float g_wt[6 * 192 * 64];                // folded weights, layout [(blk*3+l)][i*3+k][o]
__device__ float g_bias[6 * 64];                    // folded BN bias
__device__ int   g_g1[BATCH * NPTS];                // = pa1 (int32)
__device__ int   g_g2[BATCH * NPTS];                // = re1[pa2[m]] (composed gather for block 2)
__device__ int   g_s2[BATCH * NPTS];                // = pa2 (scatter index for final output)
__device__ int   g_is64;                            // index dtype flag: 1 = int64, 0 = int32

// ---- packed f32x2 helpers (FFMA2 only reachable via PTX) ----
__device__ __forceinline__ unsigned long long pk2(float lo, float hi) {
    unsigned long long r;
    asm("mov.b64 %0, {%1, %2};" : "=l"(r) : "f"(lo), "f"(hi));
    return r;
}
__device__ __forceinline__ unsigned long long fma2(unsigned long long a,
                                                   unsigned long long b,
                                                   unsigned long long c) {
    unsigned long long d;
    asm("fma.rn.f32x2 %0, %1, %2, %3;" : "=l"(d) : "l"(a), "l"(b), "l"(c));
    return d;
}
__device__ __forceinline__ float2 upk2(unsigned long long v) {
    float lo, hi;
    asm("mov.b64 {%0, %1}, %2;" : "=f"(lo), "=f"(hi) : "l"(v));
    return make_float2(lo, hi);
}

// One conv layer over the tile.
// MODE 0: ReLU -> smem dst buffer (rows 0..127 logical).
// MODE 1: final layer of block 1: relu(x + h), contiguous store to g-out.
// MODE 2: final layer of block 2: relu(x + h), scatter store via g_s2.
template <int MODE>
__device__ __forceinline__ void conv_layer(
    const float* __restrict__ src,      // padded buffer: logical row r at src[(r+1)*CH]
    float*       __restrict__ dstbuf,   // MODE 0 destination (same padded layout)
    const float* __restrict__ Ws,       // [192][64] folded weights in smem
    const float* __restrict__ Bs,       // [64] folded bias in smem
    const float* __restrict__ Xres,     // residual source (Xs) for MODE 1/2
    float*       __restrict__ gout,     // global output for MODE 1/2
    int b, int m0)
{
    const int tid = threadIdx.x;
    const int oo  = tid & 15;    // o-group: channels ob..ob+3
    const int mo  = tid >> 4;    // m-group: rows R0..R0+7
    const int ob  = oo * 4;
    const int R0  = mo * 8;

    unsigned long long acc[4][4];  // [row-pair][channel]
#pragma unroll
    for (int p = 0; p < 4; p++)
#pragma unroll
        for (int c = 0; c < 4; c++) acc[p][c] = 0ull;

    const float* xcol = src + R0 * CH;  // logical row R0-1

#pragma unroll 1
    for (int i = 0; i < CH; i += 2) {
        // 10 input rows (R0-1 .. R0+8), two channels (i, i+1) at once
        float2 xv[10];
#pragma unroll
        for (int j = 0; j < 10; j++)
            xv[j] = *reinterpret_cast<const float2*>(&xcol[j * CH + i]);

        unsigned long long P0[9], P1[9];   // adjacent-row pairs per channel
#pragma unroll
        for (int s = 0; s < 9; s++) {
            P0[s] = pk2(xv[s].x, xv[s + 1].x);
            P1[s] = pk2(xv[s].y, xv[s + 1].y);
        }

#pragma unroll
        for (int ii = 0; ii < 2; ii++) {
            const float4 w0 = *reinterpret_cast<const float4*>(&Ws[((i + ii) * 3 + 0) * CH + ob]);
            const float4 w1 = *reinterpret_cast<const float4*>(&Ws[((i + ii) * 3 + 1) * CH + ob]);
            const float4 w2 = *reinterpret_cast<const float4*>(&Ws[((i + ii) * 3 + 2) * CH + ob]);
            unsigned long long wb[3][4];
            wb[0][0] = pk2(w0.x, w0.x); wb[0][1] = pk2(w0.y, w0.y);
            wb[0][2] = pk2(w0.z, w0.z); wb[0][3] = pk2(w0.w, w0.w);
            wb[1][0] = pk2(w1.x, w1.x); wb[1][1] = pk2(w1.y, w1.y);
            wb[1][2] = pk2(w1.z, w1.z); wb[1][3] = pk2(w1.w, w1.w);
            wb[2][0] = pk2(w2.x, w2.x); wb[2][1] = pk2(w2.y, w2.y);
            wb[2][2] = pk2(w2.z, w2.z); wb[2][3] = pk2(w2.w, w2.w);

            const unsigned long long* P = ii ? P1 : P0;
#pragma unroll
            for (int p = 0; p < 4; p++)
#pragma unroll
                for (int k = 0; k < 3; k++)
#pragma unroll
                    for (int c = 0; c < 4; c++)
                        acc[p][c] = fma2(P[2 * p + k], wb[k][c], acc[p][c]);
        }
    }

    const float4 bs = *reinterpret_cast<const float4*>(&Bs[ob]);
#pragma unroll
    for (int p = 0; p < 4; p++) {
        const float2 a0 = upk2(acc[p][0]);
        const float2 a1 = upk2(acc[p][1]);
        const float2 a2 = upk2(acc[p][2]);
        const float2 a3 = upk2(acc[p][3]);
        if (MODE == 0) {
            float4 e0 = make_float4(fmaxf(a0.x + bs.x, 0.f), fmaxf(a1.x + bs.y, 0.f),
                                    fmaxf(a2.x + bs.z, 0.f), fmaxf(a3.x + bs.w, 0.f));
            float4 e1 = make_float4(fmaxf(a0.y + bs.x, 0.f), fmaxf(a1.y + bs.y, 0.f),
                                    fmaxf(a2.y + bs.z, 0.f), fmaxf(a3.y + bs.w, 0.f));
            *reinterpret_cast<float4*>(&dstbuf[(R0 + 2 * p + 1) * CH + ob]) = e0;
            *reinterpret_cast<float4*>(&dstbuf[(R0 + 2 * p + 2) * CH + ob]) = e1;
        } else {
#pragma unroll
            for (int e = 0; e < 2; e++) {
                const int r = R0 + 2 * p + e;
                if (r >= 3 && r < 3 + T) {
                    const int m = m0 - 3 + r;
                    if (m < NPTS) {
                        const float4 xr = *reinterpret_cast<const float4*>(&Xres[(r + 1) * CH + ob]);
                        const float h0 = (e ? a0.y : a0.x) + bs.x;
                        const float h1 = (e ? a1.y : a1.x) + bs.y;
                        const float h2 = (e ? a2.y : a2.x) + bs.z;
                        const float h3 = (e ? a3.y : a3.x) + bs.w;
                        float4 o4 = make_float4(fmaxf(xr.x + h0, 0.f), fmaxf(xr.y + h1, 0.f),
                                                fmaxf(xr.z + h2, 0.f), fmaxf(xr.w + h3, 0.f));
                        size_t mm = (MODE == 1) ? (size_t)m : (size_t)g_s2[b * NPTS + m];
                        *reinterpret_cast<float4*>(&gout[((size_t)b * NPTS + mm) * CH + ob]) = o4;
                    }
                }
            }
        }
    }
}

__device__ __forceinline__ void load_w(float* Ws, float* Bs, int bl, int tid) {
    const float4* src = reinterpret_cast<const float4*>(g_wt + (size_t)bl * 192 * 64);
    float4* dst = reinterpret_cast<float4*>(Ws);
    for (int q = tid; q < 192 * 64 / 4; q += 256) dst[q] = src[q];
    if (tid < 64) Bs[tid] = g_bias[bl * 64 + tid];
}

template <bool FIRST>
__global__ void __launch_bounds__(256, 1)
block_kernel(const float* __restrict__ xin, float* __restrict__ fout)
{
    extern __shared__ float smem[];
    float* Xs = smem;
    float* H1 = Xs + PADROWS * CH;
    float* H2 = H1 + PADROWS * CH;
    float* Ws = H2 + PADROWS * CH;
    float* Bs = Ws + 192 * CH;

    const int b   = blockIdx.y;
    const int m0  = blockIdx.x * T;
    const int tid = threadIdx.x;
    const float* in   = FIRST ? xin : g_h1;
    const int*   gidx = FIRST ? g_g1 : g_g2;

    // Gather input tile: logical rows 0..127, zero outside [0,N) (conv SAME padding)
    for (int q = tid; q < ROWS * 16; q += 256) {
        const int r  = q >> 4;
        const int c4 = (q & 15) << 2;
        const int m  = m0 - 3 + r;
        float4 v = make_float4(0.f, 0.f, 0.f, 0.f);
        if ((unsigned)m < (unsigned)NPTS) {
            const int p = gidx[b * NPTS + m];
            v = *reinterpret_cast<const float4*>(&in[((size_t)b * NPTS + p) * CH + c4]);
        }
        *reinterpret_cast<float4*>(&Xs[(r + 1) * CH + c4]) = v;
    }

    const int blbase = FIRST ? 0 : 3;
    load_w(Ws, Bs, blbase + 0, tid);
    __syncthreads();
    conv_layer<0>(Xs, H1, Ws, Bs, nullptr, nullptr, b, m0);
    __syncthreads();
    load_w(Ws, Bs, blbase + 1, tid);
    __syncthreads();
    conv_layer<0>(H1, H2, Ws, Bs, nullptr, nullptr, b, m0);
    __syncthreads();
    load_w(Ws, Bs, blbase + 2, tid);
    __syncthreads();
    conv_layer<FIRST ? 1 : 2>(H2, nullptr, Ws, Bs, Xs, FIRST ? g_h1 : fout, b, m0);
}

// Fold BN into weights: W'[bl][i*3+k][o] = W[bl][o][i][k] * gamma/sqrt(var+eps)
__global__ void prep_weights(const float* __restrict__ w,
                             const float* __restrict__ gamma,
                             const float* __restrict__ beta,
                             const float* __restrict__ mean,
                             const float* __restrict__ var)
{
    const int idx = blockIdx.x * 256 + threadIdx.x;
    if (idx >= 6 * 64 * 64 * 3) return;
    const int k  = idx % 3;
    const int i  = (idx / 3) % 64;
    const int o  = (idx / 192) % 64;
    const int bl = idx / 12288;
    const float sc = gamma[bl * 64 + o] * rsqrtf(var[bl * 64 + o] + 1e-5f);
    g_wt[(bl * 192 + i * 3 + k) * 64 + o] = w[idx] * sc;
    if (i == 0 && k == 0)
        g_bias[bl * 64 + o] = beta[bl * 64 + o] - mean[bl * 64 + o] * sc;
}

// Detect index dtype. For int64 little-endian, every odd 32-bit word is the
// zero hi-half (all perm values < 2^31). For an int32 permutation, at most one
// of the sampled words can be zero (values are distinct). Scan 1024 odd words.
__global__ void detect_dtype(const unsigned int* __restrict__ w)
{
    __shared__ int nz;
    if (threadIdx.x == 0) nz = 0;
    __syncthreads();
    for (int q = 2 * threadIdx.x + 1; q < 2048; q += 2 * blockDim.x)
        if (w[q] != 0u) nz = 1;          // benign race: any writer sets 1
    __syncthreads();
    if (threadIdx.x == 0) g_is64 = nz ? 0 : 1;
}

// Compose permutations: g1 = pa1, g2[m] = re1[pa2[m]], s2 = pa2.
// Index arrays decoded per detected dtype (int32 or int64).
__global__ void prep_idx(const void* __restrict__ pa1,
                         const void* __restrict__ re1,
                         const void* __restrict__ pa2)
{
    const int j = blockIdx.x * 256 + threadIdx.x;
    if (j >= BATCH * NPTS) return;
    const bool is64 = (g_is64 != 0);
    const int b = j / NPTS;

    int v_pa1, v_pa2;
    if (is64) {
        v_pa1 = (int)((const long long*)pa1)[j];
        v_pa2 = (int)((const long long*)pa2)[j];
    } else {
        v_pa1 = ((const int*)pa1)[j];
        v_pa2 = ((const int*)pa2)[j];
    }
    int v_re1;
    if (is64) v_re1 = (int)((const long long*)re1)[b * NPTS + v_pa2];
    else      v_re1 = ((const int*)re1)[b * NPTS + v_pa2];

    g_g1[j] = v_pa1;
    g_s2[j] = v_pa2;
    g_g2[j] = v_re1;
}

extern "C" void kernel_launch(void* const* d_in, const int* in_sizes, int n_in,
                              void* d_out, int out_size)
{
    const float* x      = (const float*)d_in[0];
    const void*  pa1    = d_in[1];
    const void*  re1    = d_in[2];
    const void*  pa2    = d_in[3];
    // d_in[4] (idx_re_2) is unused: final inverse-gather is done as a scatter by pa2.
    const float* conv_w = (const float*)d_in[5];
    const float* gamma  = (const float*)d_in[6];
    const float* beta   = (const float*)d_in[7];
    const float* mean   = (const float*)d_in[8];
    const float* var    = (const float*)d_in[9];
    float* out = (float*)d_out;

    detect_dtype<<<1, 256>>>((const unsigned int*)pa1);
    prep_weights<<<(6 * 64 * 64 * 3 + 255) / 256, 256>>>(conv_w, gamma, beta, mean, var);
    prep_idx<<<(BATCH * NPTS + 255) / 256, 256>>>(pa1, re1, pa2);

    const int smem_bytes = SMEM_FLOATS * (int)sizeof(float);  // ~146 KB
    cudaFuncSetAttribute(block_kernel<true>,  cudaFuncAttributeMaxDynamicSharedMemorySize, smem_bytes);
    cudaFuncSetAttribute(block_kernel<false>, cudaFuncAttributeMaxDynamicSharedMemorySize, smem_bytes);

    dim3 grid(NTILES, BATCH);
    block_kernel<true><<<grid, 256, smem_bytes>>>(x, nullptr);    // x -> g_h1 (contiguous)
    block_kernel<false><<<grid, 256, smem_bytes>>>(x, out);       // g_h1 -> out (scatter)
}